// round 10
// baseline (speedup 1.0000x reference)
#include <cuda_runtime.h>
#include <cuda_bf16.h>
#include <cstdint>
#include <float.h>

#define W 128
#define BINS 50
#define NBOUND (BINS - 1)
#define MPAD 52
#define THREADS 256
#define NWARP (THREADS / 32)   // 8
#define MAXS 1536
#define GROW (BINS * W)        // 6400 floats per series

// Global scratch (39.3 MB + 768 KB) — __device__ arrays are the sanctioned scratch path.
__device__ float g_G[MAXS * GROW];
__device__ int   g_bins[MAXS * W];

// ---------------- Kernel 1: compute bins + 50 normalized rows per series ----------------
__global__ __launch_bounds__(THREADS)
void mtf_build(const float* __restrict__ X, int S) {
    __shared__ float bnd[NBOUND];
    __shared__ __align__(16) int bins[W];
    __shared__ float mtm[BINS * MPAD];
    __shared__ float smn[NWARP], smx[NWARP];
    __shared__ float bmn, bmx;

    const int s    = blockIdx.x;
    const int tid  = threadIdx.x;
    const int lane = tid & 31;
    const int wid  = tid >> 5;
    if (s >= S) return;

    const float* x = X + (size_t)s * W;

    if (tid < NBOUND) {
        bnd[tid] = (float)(-1.0 + (2.0 * (double)(tid + 1)) / 50.0);
    }
    for (int i = tid; i < BINS * MPAD; i += THREADS) mtm[i] = 0.0f;

    float v = 0.0f;
    if (tid < W) v = x[tid];
    float mn = (tid < W) ? v : FLT_MAX;
    float mx = (tid < W) ? v : -FLT_MAX;
    #pragma unroll
    for (int o = 16; o > 0; o >>= 1) {
        mn = fminf(mn, __shfl_xor_sync(0xFFFFFFFFu, mn, o));
        mx = fmaxf(mx, __shfl_xor_sync(0xFFFFFFFFu, mx, o));
    }
    if (lane == 0) { smn[wid] = mn; smx[wid] = mx; }
    __syncthreads();
    if (wid == 0) {
        float a = (lane < NWARP) ? smn[lane] : FLT_MAX;
        float b = (lane < NWARP) ? smx[lane] : -FLT_MAX;
        #pragma unroll
        for (int o = 4; o > 0; o >>= 1) {
            a = fminf(a, __shfl_xor_sync(0xFFFFFFFFu, a, o));
            b = fmaxf(b, __shfl_xor_sync(0xFFFFFFFFu, b, o));
        }
        if (lane == 0) { bmn = a; bmx = b; }
    }
    __syncthreads();

    if (tid < W) {
        float denom = bmx - bmn + 1e-6f;
        float t = (v - bmn) / denom;
        float xsc = t * 2.0f + (-1.0f);
        int cnt = 0;
        #pragma unroll
        for (int k = 0; k < NBOUND; k++) cnt += (bnd[k] < xsc) ? 1 : 0;
        bins[tid] = cnt;
        g_bins[s * W + tid] = cnt;
    }
    __syncthreads();

    if (tid < W - 1) {
        atomicAdd(&mtm[bins[tid] * MPAD + bins[tid + 1]], 1.0f);
    }
    const int4 c = reinterpret_cast<const int4*>(bins)[lane];
    __syncthreads();

    // G[s][b1][t2] = mtm[b1][bins[t2]] / rowsum(b1)  — coalesced STG.128 rows.
    float* Gs = g_G + (size_t)s * GROW;
    for (int b1 = wid; b1 < BINS; b1 += NWARP) {
        const float* row = &mtm[b1 * MPAD];
        float part = row[lane] + ((lane < BINS - 32) ? row[lane + 32] : 0.0f);
        #pragma unroll
        for (int off = 16; off > 0; off >>= 1)
            part += __shfl_xor_sync(0xFFFFFFFFu, part, off);
        float rinv = (part == 0.0f) ? 1.0f : (1.0f / part);

        float4 val;
        val.x = row[c.x] * rinv;
        val.y = row[c.y] * rinv;
        val.z = row[c.z] * rinv;
        val.w = row[c.w] * rinv;
        reinterpret_cast<float4*>(Gs + b1 * W)[lane] = val;
    }
}

// ---------------- Kernel 2: pure streaming broadcast: out[s][t1][:] = G[s][bins[t1]][:] ----
// No smem, no barriers. One CTA per series; warp w owns rows w*16..w*16+15, 4-way MLP.
__global__ __launch_bounds__(THREADS)
void mtf_scatter(float* __restrict__ out, int S) {
    const int s    = blockIdx.x;
    const int lane = threadIdx.x & 31;
    const int wid  = threadIdx.x >> 5;
    if (s >= S) return;

    const float* Gs = g_G + (size_t)s * GROW;
    const int*   bs = g_bins + s * W;
    float* os = out + (size_t)s * W * W;

    #pragma unroll
    for (int r0 = 0; r0 < 16; r0 += 4) {
        int t1 = wid * 16 + r0;
        int b0 = bs[t1 + 0];
        int b1 = bs[t1 + 1];
        int b2 = bs[t1 + 2];
        int b3 = bs[t1 + 3];
        float4 v0 = reinterpret_cast<const float4*>(Gs + b0 * W)[lane];
        float4 v1 = reinterpret_cast<const float4*>(Gs + b1 * W)[lane];
        float4 v2 = reinterpret_cast<const float4*>(Gs + b2 * W)[lane];
        float4 v3 = reinterpret_cast<const float4*>(Gs + b3 * W)[lane];
        reinterpret_cast<float4*>(os + (t1 + 0) * W)[lane] = v0;
        reinterpret_cast<float4*>(os + (t1 + 1) * W)[lane] = v1;
        reinterpret_cast<float4*>(os + (t1 + 2) * W)[lane] = v2;
        reinterpret_cast<float4*>(os + (t1 + 3) * W)[lane] = v3;
    }
}

extern "C" void kernel_launch(void* const* d_in, const int* in_sizes, int n_in,
                              void* d_out, int out_size) {
    const float* X = (const float*)d_in[0];
    float* out = (float*)d_out;
    int S = in_sizes[0] / W;   // 1536
    mtf_build<<<S, THREADS>>>(X, S);
    mtf_scatter<<<S, THREADS>>>(out, S);
}

// round 11
// speedup vs baseline: 1.5319x; 1.5319x over previous
#include <cuda_runtime.h>
#include <cuda_bf16.h>
#include <cstdint>
#include <float.h>

#define W 128
#define BINS 50
#define NBOUND (BINS - 1)
#define MPAD 64              // padded row stride for mtm
#define THREADS 256
#define NWARP (THREADS / 32)

__global__ __launch_bounds__(THREADS, 8)
void mtf_kernel(const float* __restrict__ X, float* __restrict__ out, int S) {
    __shared__ float bnd[NBOUND];
    __shared__ int   bins[W];
    __shared__ float mtm[BINS * MPAD];     // padded: bank(c) = c mod 32
    __shared__ float smn[NWARP], smx[NWARP];
    __shared__ float bmn, bmx;

    const int s    = blockIdx.x;
    const int tid  = threadIdx.x;
    const int lane = tid & 31;
    const int wid  = tid >> 5;

    if (s >= S) return;

    const float* x = X + (size_t)s * W;

    // Boundaries: linspace(-1, 1, 51)[1:-1].
    if (tid < NBOUND) {
        bnd[tid] = (float)(-1.0 + (2.0 * (double)(tid + 1)) / 50.0);
    }
    // Zero transition counts.
    for (int i = tid; i < BINS * MPAD; i += THREADS) mtm[i] = 0.0f;

    // Load series value (threads 0..127) and block min/max.
    float v = 0.0f;
    if (tid < W) v = x[tid];
    float mn = (tid < W) ? v : FLT_MAX;
    float mx = (tid < W) ? v : -FLT_MAX;
    #pragma unroll
    for (int o = 16; o > 0; o >>= 1) {
        mn = fminf(mn, __shfl_xor_sync(0xFFFFFFFFu, mn, o));
        mx = fmaxf(mx, __shfl_xor_sync(0xFFFFFFFFu, mx, o));
    }
    if (lane == 0) { smn[wid] = mn; smx[wid] = mx; }
    __syncthreads();
    if (wid == 0) {
        float a = (lane < NWARP) ? smn[lane] : FLT_MAX;
        float b = (lane < NWARP) ? smx[lane] : -FLT_MAX;
        #pragma unroll
        for (int o = 4; o > 0; o >>= 1) {
            a = fminf(a, __shfl_xor_sync(0xFFFFFFFFu, a, o));
            b = fmaxf(b, __shfl_xor_sync(0xFFFFFFFFu, b, o));
        }
        if (lane == 0) { bmn = a; bmx = b; }
    }
    __syncthreads();

    // Scale into [-1,1] (same op order as reference) and bucketize.
    if (tid < W) {
        float denom = bmx - bmn + 1e-6f;
        float t = (v - bmn) / denom;
        float xsc = t * 2.0f + (-1.0f);
        int cnt = 0;
        #pragma unroll
        for (int k = 0; k < NBOUND; k++) cnt += (bnd[k] < xsc) ? 1 : 0;
        bins[tid] = cnt;
    }
    __syncthreads();

    // Transition histogram (padded rows).
    if (tid < W - 1) {
        atomicAdd(&mtm[bins[tid] * BINS + bins[tid + 1] + bins[tid] * (MPAD - BINS)], 1.0f);
    }
    // Every lane caches the 4 column-bin indices it is responsible for
    // (strided layout: t2 = lane, lane+32, lane+64, lane+96).
    int c0 = bins[lane];
    int c1 = bins[lane + 32];
    int c2 = bins[lane + 64];
    int c3 = bins[lane + 96];
    __syncthreads();

    // Per bin-row: ballots give BOTH the destination rows AND the row sum
    // (rowsum(b1) = #{t in 0..126 : bins[t] == b1}; t=127 is a destination
    // but never a transition source, so it is masked out of the count).
    float* o = out + (size_t)s * W * W;
    for (int b1 = wid; b1 < BINS; b1 += NWARP) {
        unsigned m0 = __ballot_sync(0xFFFFFFFFu, c0 == b1);
        unsigned m1 = __ballot_sync(0xFFFFFFFFu, c1 == b1);
        unsigned m2 = __ballot_sync(0xFFFFFFFFu, c2 == b1);
        unsigned m3 = __ballot_sync(0xFFFFFFFFu, c3 == b1);
        if ((m0 | m1 | m2 | m3) == 0u) continue;   // row never needed

        int cnt = __popc(m0) + __popc(m1) + __popc(m2) + __popc(m3 & 0x7FFFFFFFu);
        float rinv = (cnt == 0) ? 1.0f : (1.0f / (float)cnt);

        const float* row = &mtm[b1 * MPAD];
        float v0 = row[c0] * rinv;
        float v1 = row[c1] * rinv;
        float v2 = row[c2] * rinv;
        float v3 = row[c3] * rinv;

        while (m0) {
            int t1 = __ffs(m0) - 1; m0 &= m0 - 1;
            float* d = o + t1 * W + lane;
            d[0] = v0; d[32] = v1; d[64] = v2; d[96] = v3;
        }
        while (m1) {
            int t1 = 32 + __ffs(m1) - 1; m1 &= m1 - 1;
            float* d = o + t1 * W + lane;
            d[0] = v0; d[32] = v1; d[64] = v2; d[96] = v3;
        }
        while (m2) {
            int t1 = 64 + __ffs(m2) - 1; m2 &= m2 - 1;
            float* d = o + t1 * W + lane;
            d[0] = v0; d[32] = v1; d[64] = v2; d[96] = v3;
        }
        while (m3) {
            int t1 = 96 + __ffs(m3) - 1; m3 &= m3 - 1;
            float* d = o + t1 * W + lane;
            d[0] = v0; d[32] = v1; d[64] = v2; d[96] = v3;
        }
    }
}

extern "C" void kernel_launch(void* const* d_in, const int* in_sizes, int n_in,
                              void* d_out, int out_size) {
    const float* X = (const float*)d_in[0];
    float* out = (float*)d_out;
    int S = in_sizes[0] / W;   // 256*6 = 1536 series
    mtf_kernel<<<S, THREADS>>>(X, out, S);
}